// round 4
// baseline (speedup 1.0000x reference)
#include <cuda_runtime.h>
#include <cuda_bf16.h>
#include <math.h>

// Problem constants
#define PN   8
#define PF   16
#define PS   196
#define PD   1024
#define PH   8
#define PHD  128
#define PL   (1 + PF * PS)        // 3137
#define PNL  (PN * PL)            // 25096
#define PK   1024                 // GEMM K
#define PNN  1024                 // GEMM N

// ---------------------------------------------------------------------------
// Scratch (device globals — no allocation allowed in kernel_launch)
// ---------------------------------------------------------------------------
__device__ float g_t0[(size_t)PNL * PD];   // GEMM out / attention out (merged heads)
__device__ float g_x1[(size_t)PNL * PD];   // LN out
__device__ float g_q [(size_t)PNL * PD];
__device__ float g_k [(size_t)PNL * PD];
__device__ float g_v [(size_t)PNL * PD];

// ---------------------------------------------------------------------------
// SGEMM: C[M,1024] = A[M,1024] * B[1024,1024] (+ bias)
// BM=BN=128, BK=8, 256 threads, 8x8 per-thread tile, float4 loads, M-edge guard
// ---------------------------------------------------------------------------
template <bool HAS_BIAS>
__global__ __launch_bounds__(256, 2)
void sgemm128(int M, const float* __restrict__ A, const float* __restrict__ B,
              const float* __restrict__ bias, float* __restrict__ C)
{
    constexpr int BM = 128, BN = 128, BK = 8, TM = 8, TN = 8;
    __shared__ float As[BK * BM];   // transposed: As[k][m]
    __shared__ float Bs[BK * BN];   // Bs[k][n]

    const int tid  = threadIdx.x;
    const int cRow = blockIdx.y;
    const int cCol = blockIdx.x;

    const int tRow = tid / (BN / TN);   // 0..15
    const int tCol = tid % (BN / TN);   // 0..15

    // A tile loads: 128x8 floats = 256 float4; thread -> (row, col4)
    const int aRow = tid >> 1;          // 0..127
    const int aCol = (tid & 1) * 4;     // 0 or 4
    // B tile loads: 8x128 floats = 256 float4
    const int bRow = tid >> 5;          // 0..7
    const int bCol = (tid & 31) * 4;    // 0..124

    const int  gARow  = cRow * BM + aRow;
    const bool aValid = (gARow < M);
    const float* Aptr = A + (size_t)gARow * PK + aCol;
    const float* Bptr = B + (size_t)bRow * PNN + cCol * BN + bCol;

    float acc[TM][TN];
    #pragma unroll
    for (int i = 0; i < TM; i++)
        #pragma unroll
        for (int j = 0; j < TN; j++) acc[i][j] = 0.0f;

    float regM[TM], regN[TN];

    for (int k0 = 0; k0 < PK; k0 += BK) {
        float4 a4 = aValid ? *(const float4*)(Aptr + k0)
                           : make_float4(0.f, 0.f, 0.f, 0.f);
        float4 b4 = *(const float4*)(Bptr + (size_t)k0 * PNN);

        As[(aCol + 0) * BM + aRow] = a4.x;
        As[(aCol + 1) * BM + aRow] = a4.y;
        As[(aCol + 2) * BM + aRow] = a4.z;
        As[(aCol + 3) * BM + aRow] = a4.w;
        *(float4*)(&Bs[bRow * BN + bCol]) = b4;
        __syncthreads();

        #pragma unroll
        for (int kk = 0; kk < BK; kk++) {
            #pragma unroll
            for (int i = 0; i < TM; i++) regM[i] = As[kk * BM + tRow * TM + i];
            #pragma unroll
            for (int j = 0; j < TN; j++) regN[j] = Bs[kk * BN + tCol * TN + j];
            #pragma unroll
            for (int i = 0; i < TM; i++)
                #pragma unroll
                for (int j = 0; j < TN; j++)
                    acc[i][j] = fmaf(regM[i], regN[j], acc[i][j]);
        }
        __syncthreads();
    }

    // Epilogue
    for (int i = 0; i < TM; i++) {
        const int m = cRow * BM + tRow * TM + i;
        if (m >= M) break;
        float* Crow = C + (size_t)m * PNN + cCol * BN + tCol * TN;
        #pragma unroll
        for (int j = 0; j < TN; j += 4) {
            float4 v;
            v.x = acc[i][j + 0]; v.y = acc[i][j + 1];
            v.z = acc[i][j + 2]; v.w = acc[i][j + 3];
            if (HAS_BIAS) {
                const int col = cCol * BN + tCol * TN + j;
                v.x += bias[col + 0]; v.y += bias[col + 1];
                v.z += bias[col + 2]; v.w += bias[col + 3];
            }
            *(float4*)(Crow + j) = v;
        }
    }
}

// ---------------------------------------------------------------------------
// LayerNorm over rows of 1024 (one block per row, 256 threads, float4)
// ---------------------------------------------------------------------------
__global__ __launch_bounds__(256)
void ln_kernel(const float* __restrict__ in, const float* __restrict__ gamma,
               const float* __restrict__ beta, float* __restrict__ out)
{
    const int row = blockIdx.x;
    const int t   = threadIdx.x;
    const float4* x4 = (const float4*)(in + (size_t)row * PD);
    float4 xv = x4[t];

    float s  = xv.x + xv.y + xv.z + xv.w;
    float s2 = xv.x * xv.x + xv.y * xv.y + xv.z * xv.z + xv.w * xv.w;

    // block reduce (sum, sumsq)
    __shared__ float red[2][8];
    #pragma unroll
    for (int o = 16; o > 0; o >>= 1) {
        s  += __shfl_down_sync(0xFFFFFFFFu, s,  o);
        s2 += __shfl_down_sync(0xFFFFFFFFu, s2, o);
    }
    const int wid = t >> 5, lid = t & 31;
    if (lid == 0) { red[0][wid] = s; red[1][wid] = s2; }
    __syncthreads();
    if (wid == 0) {
        float a = (lid < 8) ? red[0][lid] : 0.f;
        float b = (lid < 8) ? red[1][lid] : 0.f;
        #pragma unroll
        for (int o = 4; o > 0; o >>= 1) {
            a += __shfl_down_sync(0xFFFFFFFFu, a, o);
            b += __shfl_down_sync(0xFFFFFFFFu, b, o);
        }
        if (lid == 0) { red[0][0] = a; red[1][0] = b; }
    }
    __syncthreads();

    const float mean = red[0][0] * (1.0f / PD);
    const float var  = red[1][0] * (1.0f / PD) - mean * mean;
    const float rstd = rsqrtf(var + 1e-5f);

    float4 gv = ((const float4*)gamma)[t];
    float4 bv = ((const float4*)beta)[t];
    float4 ov;
    ov.x = (xv.x - mean) * rstd * gv.x + bv.x;
    ov.y = (xv.y - mean) * rstd * gv.y + bv.y;
    ov.z = (xv.z - mean) * rstd * gv.z + bv.z;
    ov.w = (xv.w - mean) * rstd * gv.w + bv.w;
    ((float4*)(out + (size_t)row * PD))[t] = ov;
}

// ---------------------------------------------------------------------------
// Temporal attention (att_type == 1)
// One block per (head-idx nh in [0,64), spatial s in [0,196)); 128 threads.
// q: 16 frames x 128; k/v: feature token + 16 frames = 17 x 128.
//
// IMPORTANT reference quirk: fk = jnp.tile(feat_k, (S,1,1)) CONCATENATES S
// copies along axis 0, so attention batch b = nh*S + s receives the feature
// K/V of head-batch (b % 64) = (4*nh + s) % 64 — NOT its own nh. The feat_q
// passthrough (output token 0) IS the own (n,h) row (no tiling there).
// ---------------------------------------------------------------------------
__global__ __launch_bounds__(128)
void attn_kernel(const float* __restrict__ Q, const float* __restrict__ Kt,
                 const float* __restrict__ Vt, float* __restrict__ O)
{
    constexpr int PITCH = 129;  // pad to avoid 32-way conflicts in score loop
    __shared__ float qs[16 * PITCH];
    __shared__ float ks[17 * PITCH];
    __shared__ float vs[17 * PITCH];
    __shared__ float ps[16 * 18];

    const int s  = blockIdx.x;         // 0..195
    const int nh = blockIdx.y;         // 0..63
    const int n  = nh >> 3;
    const int h  = nh & 7;
    const int t  = threadIdx.x;        // 0..127

    // feature K/V come from the tile-aliased batch (nh*S + s) mod 64
    const int fb = (nh * PS + s) & 63;
    const int fn = fb >> 3;
    const int fh = fb & 7;
    const size_t featKV = ((size_t)fn * PL) * PD + (size_t)fh * PHD;
    ks[t] = Kt[featKV + t];
    vs[t] = Vt[featKV + t];

    for (int f = 0; f < PF; f++) {
        const size_t r = ((size_t)n * PL + 1 + (size_t)f * PS + s) * PD + (size_t)h * PHD;
        qs[f * PITCH + t]       = Q [r + t];
        ks[(f + 1) * PITCH + t] = Kt[r + t];
        vs[(f + 1) * PITCH + t] = Vt[r + t];
    }
    __syncthreads();

    // scores: 16 x 17 dot products of length 128
    const float scale = 0.088388347648318447f;   // 1/sqrt(128)
    for (int p = t; p < 16 * 17; p += 128) {
        const int i = p / 17, j = p % 17;
        float acc = 0.f;
        #pragma unroll 8
        for (int d = 0; d < PHD; d++)
            acc = fmaf(qs[i * PITCH + d], ks[j * PITCH + d], acc);
        ps[i * 18 + j] = acc * scale;
    }
    __syncthreads();

    // softmax over 17 (one thread per query row)
    if (t < 16) {
        float mx = -1e30f;
        #pragma unroll
        for (int j = 0; j < 17; j++) mx = fmaxf(mx, ps[t * 18 + j]);
        float sum = 0.f;
        #pragma unroll
        for (int j = 0; j < 17; j++) {
            const float e = __expf(ps[t * 18 + j] - mx);
            ps[t * 18 + j] = e;
            sum += e;
        }
        const float inv = 1.0f / sum;
        #pragma unroll
        for (int j = 0; j < 17; j++) ps[t * 18 + j] *= inv;
    }
    __syncthreads();

    // out[i][d] = sum_j p[i][j] * v[j][d]; thread t owns column d=t
    for (int i = 0; i < PF; i++) {
        float acc = 0.f;
        #pragma unroll
        for (int j = 0; j < 17; j++)
            acc = fmaf(ps[i * 18 + j], vs[j * PITCH + t], acc);
        O[((size_t)n * PL + 1 + (size_t)i * PS + s) * PD + (size_t)h * PHD + t] = acc;
    }

    // feature-token passthrough: out[:, 0] = q[:, 0]  (own (n,h) row, NOT tiled)
    if (s == 0) {
        const size_t featRow = ((size_t)n * PL) * PD + (size_t)h * PHD;
        O[featRow + t] = Q[featRow + t];
    }
}

// ---------------------------------------------------------------------------
// Launch
// ---------------------------------------------------------------------------
extern "C" void kernel_launch(void* const* d_in, const int* in_sizes, int n_in,
                              void* d_out, int out_size)
{
    (void)in_sizes; (void)n_in; (void)out_size;

    const float* x        = (const float*)d_in[0];
    const float* W_in     = (const float*)d_in[1];
    const float* b_in     = (const float*)d_in[2];
    const float* g_in     = (const float*)d_in[3];
    const float* beta_in  = (const float*)d_in[4];
    const float* W_q      = (const float*)d_in[5];
    const float* W_k      = (const float*)d_in[6];
    const float* W_v      = (const float*)d_in[7];
    const float* g_out    = (const float*)d_in[8];
    const float* beta_out = (const float*)d_in[9];
    const float* W_out    = (const float*)d_in[10];
    const float* b_out    = (const float*)d_in[11];
    float* out = (float*)d_out;

    float *t0 = nullptr, *x1 = nullptr, *q = nullptr, *k = nullptr, *v = nullptr;
    cudaGetSymbolAddress((void**)&t0, g_t0);
    cudaGetSymbolAddress((void**)&x1, g_x1);
    cudaGetSymbolAddress((void**)&q,  g_q);
    cudaGetSymbolAddress((void**)&k,  g_k);
    cudaGetSymbolAddress((void**)&v,  g_v);

    const dim3 gemmGrid(PNN / 128, (PNL + 127) / 128);   // (8, 197)
    const dim3 gemmBlk(256);

    // 1. t0 = x @ W_in + b_in
    sgemm128<true ><<<gemmGrid, gemmBlk>>>(PNL, x, W_in, b_in, t0);
    // 2. x1 = LN(t0; g_in, beta_in)
    ln_kernel<<<PNL, 256>>>(t0, g_in, beta_in, x1);
    // 3. q/k/v projections
    sgemm128<false><<<gemmGrid, gemmBlk>>>(PNL, x1, W_q, nullptr, q);
    sgemm128<false><<<gemmGrid, gemmBlk>>>(PNL, x1, W_k, nullptr, k);
    sgemm128<false><<<gemmGrid, gemmBlk>>>(PNL, x1, W_v, nullptr, v);
    // 4. temporal attention (+ feature-token passthrough), merged heads -> t0
    attn_kernel<<<dim3(PS, PN * PH), 128>>>(q, k, v, t0);
    // 5. x1 = LN(t0; g_out, beta_out)
    ln_kernel<<<PNL, 256>>>(t0, g_out, beta_out, x1);
    // 6. out = x1 @ W_out + b_out
    sgemm128<true ><<<gemmGrid, gemmBlk>>>(PNL, x1, W_out, b_out, out);
}

// round 6
// speedup vs baseline: 2.4812x; 2.4812x over previous
#include <cuda_runtime.h>
#include <cuda_bf16.h>
#include <cstdint>
#include <math.h>

// Problem constants
#define PN   8
#define PF   16
#define PS   196
#define PD   1024
#define PH   8
#define PHD  128
#define PL   (1 + PF * PS)        // 3137
#define PNL  (PN * PL)            // 25096

// ---------------------------------------------------------------------------
// Scratch (device globals)
// ---------------------------------------------------------------------------
__device__ float g_t0[(size_t)PNL * PD];
__device__ float g_x1[(size_t)PNL * PD];
__device__ float g_q [(size_t)PNL * PD];
__device__ float g_k [(size_t)PNL * PD];
__device__ float g_v [(size_t)PNL * PD];
__device__ __nv_bfloat16 g_ahi[(size_t)PNL * PD];
__device__ __nv_bfloat16 g_alo[(size_t)PNL * PD];
__device__ __nv_bfloat16 g_wth[5ull * 1024 * 1024];  // 5 transposed weights, hi
__device__ __nv_bfloat16 g_wtl[5ull * 1024 * 1024];  // lo

// ---------------------------------------------------------------------------
// Helpers
// ---------------------------------------------------------------------------
__device__ __forceinline__ uint32_t smem_u32(const void* p) {
    uint32_t a;
    asm("{ .reg .u64 t; cvta.to.shared.u64 t, %1; cvt.u32.u64 %0, t; }" : "=r"(a) : "l"(p));
    return a;
}

#define LDM_X4(d0, d1, d2, d3, addr)                                             \
    asm volatile("ldmatrix.sync.aligned.m8n8.x4.shared.b16 {%0,%1,%2,%3}, [%4];" \
                 : "=r"(d0), "=r"(d1), "=r"(d2), "=r"(d3) : "r"(addr))
#define LDM_X2(d0, d1, addr)                                                     \
    asm volatile("ldmatrix.sync.aligned.m8n8.x2.shared.b16 {%0,%1}, [%2];"       \
                 : "=r"(d0), "=r"(d1) : "r"(addr))
#define MMA_BF16(d, a, b)                                                        \
    asm volatile("mma.sync.aligned.m16n8k16.row.col.f32.bf16.bf16.f32 "          \
                 "{%0,%1,%2,%3}, {%4,%5,%6,%7}, {%8,%9}, {%0,%1,%2,%3};"         \
                 : "+f"((d)[0]), "+f"((d)[1]), "+f"((d)[2]), "+f"((d)[3])        \
                 : "r"((a)[0]), "r"((a)[1]), "r"((a)[2]), "r"((a)[3]),           \
                   "r"((b)[0]), "r"((b)[1]))

// ---------------------------------------------------------------------------
// Split fp32 -> bf16 hi + lo (elementwise, float4)
// ---------------------------------------------------------------------------
__global__ __launch_bounds__(256)
void split_kernel(const float* __restrict__ in, __nv_bfloat16* __restrict__ hi,
                  __nv_bfloat16* __restrict__ lo, int n4)
{
    int i = blockIdx.x * blockDim.x + threadIdx.x;
    if (i >= n4) return;
    float4 x = ((const float4*)in)[i];
    __nv_bfloat16 h0 = __float2bfloat16_rn(x.x);
    __nv_bfloat16 h1 = __float2bfloat16_rn(x.y);
    __nv_bfloat16 h2 = __float2bfloat16_rn(x.z);
    __nv_bfloat16 h3 = __float2bfloat16_rn(x.w);
    __nv_bfloat16 l0 = __float2bfloat16_rn(x.x - __bfloat162float(h0));
    __nv_bfloat16 l1 = __float2bfloat16_rn(x.y - __bfloat162float(h1));
    __nv_bfloat16 l2 = __float2bfloat16_rn(x.z - __bfloat162float(h2));
    __nv_bfloat16 l3 = __float2bfloat16_rn(x.w - __bfloat162float(h3));
    ((__nv_bfloat162*)hi)[2 * i]     = __nv_bfloat162(h0, h1);
    ((__nv_bfloat162*)hi)[2 * i + 1] = __nv_bfloat162(h2, h3);
    ((__nv_bfloat162*)lo)[2 * i]     = __nv_bfloat162(l0, l1);
    ((__nv_bfloat162*)lo)[2 * i + 1] = __nv_bfloat162(l2, l3);
}

// ---------------------------------------------------------------------------
// Transpose + split weight: W[k][n] fp32 -> Wt_hi[n][k], Wt_lo[n][k] bf16
// ---------------------------------------------------------------------------
__global__ __launch_bounds__(256)
void wsplit_kernel(const float* __restrict__ W, __nv_bfloat16* __restrict__ hi,
                   __nv_bfloat16* __restrict__ lo)
{
    __shared__ float t[32][33];
    const int bx = blockIdx.x, by = blockIdx.y;
    const int tx = threadIdx.x, ty = threadIdx.y;   // 32 x 8
    #pragma unroll
    for (int i = 0; i < 32; i += 8)
        t[ty + i][tx] = W[(size_t)(by * 32 + ty + i) * 1024 + bx * 32 + tx];
    __syncthreads();
    #pragma unroll
    for (int i = 0; i < 32; i += 8) {
        float v = t[tx][ty + i];
        __nv_bfloat16 h = __float2bfloat16_rn(v);
        __nv_bfloat16 l = __float2bfloat16_rn(v - __bfloat162float(h));
        size_t o = (size_t)(bx * 32 + ty + i) * 1024 + by * 32 + tx;
        hi[o] = h;
        lo[o] = l;
    }
}

// ---------------------------------------------------------------------------
// Warp-MMA bf16-split GEMM: C[M,1024] = A[M,1024] * Bt[1024,1024]^T (+bias)
// A as (aHi, aLo) [M][1024] bf16 row-major; B as (btHi, btLo) [n][k] (=B^T).
// Tile 128x128, BK=32; 8 warps in 2(M)x4(N), each warp 64x32 via 4x4 m16n8k16.
// Per chunk, 3 passes: Ah*Bh, Ah*Bl, Al*Bh (fp32 accum).
// ---------------------------------------------------------------------------
#define ST 40   // smem stride in bf16 (80B): conflict-free ldmatrix, 16B aligned

__global__ __launch_bounds__(256)
void gemm_mma(int M, const __nv_bfloat16* __restrict__ aHi, const __nv_bfloat16* __restrict__ aLo,
              const __nv_bfloat16* __restrict__ btHi, const __nv_bfloat16* __restrict__ btLo,
              const float* __restrict__ bias, float* __restrict__ C)
{
    __shared__ __nv_bfloat16 sAh[128 * ST], sAl[128 * ST];
    __shared__ __nv_bfloat16 sBh[128 * ST], sBl[128 * ST];

    const int tid  = threadIdx.x;
    const int wid  = tid >> 5, lane = tid & 31;
    const int m0   = blockIdx.y * 128, n0 = blockIdx.x * 128;
    const int wm   = (wid >> 2) * 64;     // warp M origin (2 warps in M)
    const int wn   = (wid & 3) * 32;      // warp N origin (4 warps in N)

    float acc[4][4][4];
    #pragma unroll
    for (int mt = 0; mt < 4; mt++)
        #pragma unroll
        for (int nt = 0; nt < 4; nt++)
            #pragma unroll
            for (int e = 0; e < 4; e++) acc[mt][nt][e] = 0.0f;

    // gmem->reg prefetch: 512 16B chunks per tile; thread does idx = tid + i*256
    // row = idx>>2 (0..127), c16 = idx&3 -> k offset c16*8 bf16
    uint4 pAh[2], pAl[2], pBh[2], pBl[2];

    #define LOAD_CHUNK(c) do {                                                   \
        const int kk0 = (c) * 32;                                                \
        _Pragma("unroll")                                                        \
        for (int i = 0; i < 2; i++) {                                            \
            int idx = tid + i * 256;                                             \
            int row = idx >> 2;                                                  \
            int kc  = kk0 + (idx & 3) * 8;                                       \
            int m   = m0 + row;                                                  \
            if (m < M) {                                                         \
                pAh[i] = *(const uint4*)(aHi + (size_t)m * 1024 + kc);           \
                pAl[i] = *(const uint4*)(aLo + (size_t)m * 1024 + kc);           \
            } else {                                                             \
                pAh[i] = make_uint4(0, 0, 0, 0);                                 \
                pAl[i] = make_uint4(0, 0, 0, 0);                                 \
            }                                                                    \
            pBh[i] = *(const uint4*)(btHi + (size_t)(n0 + row) * 1024 + kc);     \
            pBl[i] = *(const uint4*)(btLo + (size_t)(n0 + row) * 1024 + kc);     \
        }                                                                        \
    } while (0)

    LOAD_CHUNK(0);

    // ldmatrix base offsets (bytes handled via bf16 indices * 2 at use site)
    const uint32_t baseAh = smem_u32(sAh), baseAl = smem_u32(sAl);
    const uint32_t baseBh = smem_u32(sBh), baseBl = smem_u32(sBl);
    const int aRow = wm + (lane & 15);
    const int aKof = (lane >> 4) * 8;
    const int l16  = lane & 15;
    const int bRow = wn + (l16 & 7);
    const int bKof = ((l16 >> 3) & 1) * 8;

    for (int c = 0; c < 32; c++) {
        // store prefetched chunk to smem
        #pragma unroll
        for (int i = 0; i < 2; i++) {
            int idx = tid + i * 256;
            int row = idx >> 2;
            int col = (idx & 3) * 8;
            *(uint4*)&sAh[row * ST + col] = pAh[i];
            *(uint4*)&sAl[row * ST + col] = pAl[i];
            *(uint4*)&sBh[row * ST + col] = pBh[i];
            *(uint4*)&sBl[row * ST + col] = pBl[i];
        }
        __syncthreads();

        if (c < 31) LOAD_CHUNK(c + 1);   // LDG in flight during MMA

        #pragma unroll
        for (int ks = 0; ks < 2; ks++) {
            const int kb = ks * 16;
            uint32_t ah[4][4], al[4][4], bh[4][2], bl[4][2];
            #pragma unroll
            for (int mt = 0; mt < 4; mt++) {
                uint32_t off = ((aRow + mt * 16) * ST + kb + aKof) * 2;
                LDM_X4(ah[mt][0], ah[mt][1], ah[mt][2], ah[mt][3], baseAh + off);
                LDM_X4(al[mt][0], al[mt][1], al[mt][2], al[mt][3], baseAl + off);
            }
            #pragma unroll
            for (int nt = 0; nt < 4; nt++) {
                uint32_t off = ((bRow + nt * 8) * ST + kb + bKof) * 2;
                LDM_X2(bh[nt][0], bh[nt][1], baseBh + off);
                LDM_X2(bl[nt][0], bl[nt][1], baseBl + off);
            }
            #pragma unroll
            for (int mt = 0; mt < 4; mt++)
                #pragma unroll
                for (int nt = 0; nt < 4; nt++) {
                    MMA_BF16(acc[mt][nt], ah[mt], bh[nt]);
                    MMA_BF16(acc[mt][nt], ah[mt], bl[nt]);
                    MMA_BF16(acc[mt][nt], al[mt], bh[nt]);
                }
        }
        __syncthreads();
    }
    #undef LOAD_CHUNK

    // epilogue: acc[mt][nt] = m16n8 tile at (m0+wm+mt*16, n0+wn+nt*8)
    const int r     = lane >> 2;
    const int cpair = (lane & 3) * 2;
    #pragma unroll
    for (int nt = 0; nt < 4; nt++) {
        const int n  = n0 + wn + nt * 8 + cpair;
        float b0 = 0.f, b1 = 0.f;
        if (bias) { b0 = bias[n]; b1 = bias[n + 1]; }
        #pragma unroll
        for (int mt = 0; mt < 4; mt++) {
            const int m = m0 + wm + mt * 16 + r;
            if (m < M) {
                float2 v0 = make_float2(acc[mt][nt][0] + b0, acc[mt][nt][1] + b1);
                *(float2*)(C + (size_t)m * 1024 + n) = v0;
            }
            if (m + 8 < M) {
                float2 v1 = make_float2(acc[mt][nt][2] + b0, acc[mt][nt][3] + b1);
                *(float2*)(C + (size_t)(m + 8) * 1024 + n) = v1;
            }
        }
    }
}

// ---------------------------------------------------------------------------
// LayerNorm over rows of 1024 (one block per row, 256 threads, float4)
// ---------------------------------------------------------------------------
__global__ __launch_bounds__(256)
void ln_kernel(const float* __restrict__ in, const float* __restrict__ gamma,
               const float* __restrict__ beta, float* __restrict__ out)
{
    const int row = blockIdx.x;
    const int t   = threadIdx.x;
    const float4* x4 = (const float4*)(in + (size_t)row * PD);
    float4 xv = x4[t];

    float s  = xv.x + xv.y + xv.z + xv.w;
    float s2 = xv.x * xv.x + xv.y * xv.y + xv.z * xv.z + xv.w * xv.w;

    __shared__ float red[2][8];
    #pragma unroll
    for (int o = 16; o > 0; o >>= 1) {
        s  += __shfl_down_sync(0xFFFFFFFFu, s,  o);
        s2 += __shfl_down_sync(0xFFFFFFFFu, s2, o);
    }
    const int wid = t >> 5, lid = t & 31;
    if (lid == 0) { red[0][wid] = s; red[1][wid] = s2; }
    __syncthreads();
    if (wid == 0) {
        float a = (lid < 8) ? red[0][lid] : 0.f;
        float b = (lid < 8) ? red[1][lid] : 0.f;
        #pragma unroll
        for (int o = 4; o > 0; o >>= 1) {
            a += __shfl_down_sync(0xFFFFFFFFu, a, o);
            b += __shfl_down_sync(0xFFFFFFFFu, b, o);
        }
        if (lid == 0) { red[0][0] = a; red[1][0] = b; }
    }
    __syncthreads();

    const float mean = red[0][0] * (1.0f / PD);
    const float var  = red[1][0] * (1.0f / PD) - mean * mean;
    const float rstd = rsqrtf(var + 1e-5f);

    float4 gv = ((const float4*)gamma)[t];
    float4 bv = ((const float4*)beta)[t];
    float4 ov;
    ov.x = (xv.x - mean) * rstd * gv.x + bv.x;
    ov.y = (xv.y - mean) * rstd * gv.y + bv.y;
    ov.z = (xv.z - mean) * rstd * gv.z + bv.z;
    ov.w = (xv.w - mean) * rstd * gv.w + bv.w;
    ((float4*)(out + (size_t)row * PD))[t] = ov;
}

// ---------------------------------------------------------------------------
// Temporal attention (att_type == 1). Reference tile quirk: feature K/V for
// attention batch b = nh*S + s comes from head-batch (b % 64).
// ---------------------------------------------------------------------------
__global__ __launch_bounds__(128)
void attn_kernel(const float* __restrict__ Q, const float* __restrict__ Kt,
                 const float* __restrict__ Vt, float* __restrict__ O)
{
    constexpr int PITCH = 129;
    __shared__ float qs[16 * PITCH];
    __shared__ float ks[17 * PITCH];
    __shared__ float vs[17 * PITCH];
    __shared__ float ps[16 * 18];

    const int s  = blockIdx.x;         // 0..195
    const int nh = blockIdx.y;         // 0..63
    const int n  = nh >> 3;
    const int h  = nh & 7;
    const int t  = threadIdx.x;        // 0..127

    const int fb = (nh * PS + s) & 63;
    const int fn = fb >> 3;
    const int fh = fb & 7;
    const size_t featKV = ((size_t)fn * PL) * PD + (size_t)fh * PHD;
    ks[t] = Kt[featKV + t];
    vs[t] = Vt[featKV + t];

    for (int f = 0; f < PF; f++) {
        const size_t r = ((size_t)n * PL + 1 + (size_t)f * PS + s) * PD + (size_t)h * PHD;
        qs[f * PITCH + t]       = Q [r + t];
        ks[(f + 1) * PITCH + t] = Kt[r + t];
        vs[(f + 1) * PITCH + t] = Vt[r + t];
    }
    __syncthreads();

    const float scale = 0.088388347648318447f;   // 1/sqrt(128)
    for (int p = t; p < 16 * 17; p += 128) {
        const int i = p / 17, j = p % 17;
        float acc = 0.f;
        #pragma unroll 8
        for (int d = 0; d < PHD; d++)
            acc = fmaf(qs[i * PITCH + d], ks[j * PITCH + d], acc);
        ps[i * 18 + j] = acc * scale;
    }
    __syncthreads();

    if (t < 16) {
        float mx = -1e30f;
        #pragma unroll
        for (int j = 0; j < 17; j++) mx = fmaxf(mx, ps[t * 18 + j]);
        float sum = 0.f;
        #pragma unroll
        for (int j = 0; j < 17; j++) {
            const float e = __expf(ps[t * 18 + j] - mx);
            ps[t * 18 + j] = e;
            sum += e;
        }
        const float inv = 1.0f / sum;
        #pragma unroll
        for (int j = 0; j < 17; j++) ps[t * 18 + j] *= inv;
    }
    __syncthreads();

    for (int i = 0; i < PF; i++) {
        float acc = 0.f;
        #pragma unroll
        for (int j = 0; j < 17; j++)
            acc = fmaf(ps[i * 18 + j], vs[j * PITCH + t], acc);
        O[((size_t)n * PL + 1 + (size_t)i * PS + s) * PD + (size_t)h * PHD + t] = acc;
    }

    if (s == 0) {
        const size_t featRow = ((size_t)n * PL) * PD + (size_t)h * PHD;
        O[featRow + t] = Q[featRow + t];
    }
}

// ---------------------------------------------------------------------------
// Launch
// ---------------------------------------------------------------------------
extern "C" void kernel_launch(void* const* d_in, const int* in_sizes, int n_in,
                              void* d_out, int out_size)
{
    (void)in_sizes; (void)n_in; (void)out_size;

    const float* x        = (const float*)d_in[0];
    const float* W_in     = (const float*)d_in[1];
    const float* b_in     = (const float*)d_in[2];
    const float* g_in     = (const float*)d_in[3];
    const float* beta_in  = (const float*)d_in[4];
    const float* W_q      = (const float*)d_in[5];
    const float* W_k      = (const float*)d_in[6];
    const float* W_v      = (const float*)d_in[7];
    const float* g_out    = (const float*)d_in[8];
    const float* beta_out = (const float*)d_in[9];
    const float* W_out    = (const float*)d_in[10];
    const float* b_out    = (const float*)d_in[11];
    float* out = (float*)d_out;

    float *t0, *x1, *q, *k, *v;
    __nv_bfloat16 *ahi, *alo, *wth, *wtl;
    cudaGetSymbolAddress((void**)&t0,  g_t0);
    cudaGetSymbolAddress((void**)&x1,  g_x1);
    cudaGetSymbolAddress((void**)&q,   g_q);
    cudaGetSymbolAddress((void**)&k,   g_k);
    cudaGetSymbolAddress((void**)&v,   g_v);
    cudaGetSymbolAddress((void**)&ahi, g_ahi);
    cudaGetSymbolAddress((void**)&alo, g_alo);
    cudaGetSymbolAddress((void**)&wth, g_wth);
    cudaGetSymbolAddress((void**)&wtl, g_wtl);

    const size_t WSLOT = 1024ull * 1024ull;
    const dim3 wsGrid(32, 32), wsBlk(32, 8);
    const int n4 = PNL * PD / 4;
    const int splitBlocks = (n4 + 255) / 256;
    const dim3 gemmGrid(8, 197);      // (N-tiles, M-tiles)
    const dim3 gemmBlk(256);

    // weight transforms (all 5 upfront)
    wsplit_kernel<<<wsGrid, wsBlk>>>(W_in,  wth + 0 * WSLOT, wtl + 0 * WSLOT);
    wsplit_kernel<<<wsGrid, wsBlk>>>(W_q,   wth + 1 * WSLOT, wtl + 1 * WSLOT);
    wsplit_kernel<<<wsGrid, wsBlk>>>(W_k,   wth + 2 * WSLOT, wtl + 2 * WSLOT);
    wsplit_kernel<<<wsGrid, wsBlk>>>(W_v,   wth + 3 * WSLOT, wtl + 3 * WSLOT);
    wsplit_kernel<<<wsGrid, wsBlk>>>(W_out, wth + 4 * WSLOT, wtl + 4 * WSLOT);

    // 1. t0 = x @ W_in + b_in
    split_kernel<<<splitBlocks, 256>>>(x, ahi, alo, n4);
    gemm_mma<<<gemmGrid, gemmBlk>>>(PNL, ahi, alo, wth + 0 * WSLOT, wtl + 0 * WSLOT, b_in, t0);
    // 2. x1 = LN(t0)
    ln_kernel<<<PNL, 256>>>(t0, g_in, beta_in, x1);
    // 3. q/k/v projections (one split serves 3 GEMMs)
    split_kernel<<<splitBlocks, 256>>>(x1, ahi, alo, n4);
    gemm_mma<<<gemmGrid, gemmBlk>>>(PNL, ahi, alo, wth + 1 * WSLOT, wtl + 1 * WSLOT, nullptr, q);
    gemm_mma<<<gemmGrid, gemmBlk>>>(PNL, ahi, alo, wth + 2 * WSLOT, wtl + 2 * WSLOT, nullptr, k);
    gemm_mma<<<gemmGrid, gemmBlk>>>(PNL, ahi, alo, wth + 3 * WSLOT, wtl + 3 * WSLOT, nullptr, v);
    // 4. temporal attention -> t0
    attn_kernel<<<dim3(PS, PN * PH), 128>>>(q, k, v, t0);
    // 5. x1 = LN(t0)
    ln_kernel<<<PNL, 256>>>(t0, g_out, beta_out, x1);
    // 6. out = x1 @ W_out + b_out
    split_kernel<<<splitBlocks, 256>>>(x1, ahi, alo, n4);
    gemm_mma<<<gemmGrid, gemmBlk>>>(PNL, ahi, alo, wth + 4 * WSLOT, wtl + 4 * WSLOT, b_out, out);
}

// round 7
// speedup vs baseline: 2.9325x; 1.1819x over previous
#include <cuda_runtime.h>
#include <cuda_bf16.h>
#include <cstdint>
#include <math.h>

// Problem constants
#define PN   8
#define PF   16
#define PS   196
#define PD   1024
#define PH   8
#define PHD  128
#define PL   (1 + PF * PS)        // 3137
#define PNL  (PN * PL)            // 25096

// ---------------------------------------------------------------------------
// Scratch (device globals)
// ---------------------------------------------------------------------------
__device__ float g_t0[(size_t)PNL * PD];
__device__ float g_q [(size_t)PNL * PD];
__device__ float g_k [(size_t)PNL * PD];
__device__ float g_v [(size_t)PNL * PD];
__device__ __nv_bfloat16 g_ahi[(size_t)PNL * PD];
__device__ __nv_bfloat16 g_alo[(size_t)PNL * PD];
__device__ __nv_bfloat16 g_wth[5ull * 1024 * 1024];  // 5 transposed weights, hi
__device__ __nv_bfloat16 g_wtl[5ull * 1024 * 1024];  // lo

// ---------------------------------------------------------------------------
// Helpers
// ---------------------------------------------------------------------------
__device__ __forceinline__ uint32_t smem_u32(const void* p) {
    uint32_t a;
    asm("{ .reg .u64 t; cvta.to.shared.u64 t, %1; cvt.u32.u64 %0, t; }" : "=r"(a) : "l"(p));
    return a;
}

#define LDM_X4(d0, d1, d2, d3, addr)                                             \
    asm volatile("ldmatrix.sync.aligned.m8n8.x4.shared.b16 {%0,%1,%2,%3}, [%4];" \
                 : "=r"(d0), "=r"(d1), "=r"(d2), "=r"(d3) : "r"(addr))
#define MMA_BF16(d, a, b0, b1)                                                   \
    asm volatile("mma.sync.aligned.m16n8k16.row.col.f32.bf16.bf16.f32 "          \
                 "{%0,%1,%2,%3}, {%4,%5,%6,%7}, {%8,%9}, {%0,%1,%2,%3};"         \
                 : "+f"((d)[0]), "+f"((d)[1]), "+f"((d)[2]), "+f"((d)[3])        \
                 : "r"((a)[0]), "r"((a)[1]), "r"((a)[2]), "r"((a)[3]),           \
                   "r"(b0), "r"(b1))
#define CP_ASYNC16(dst, src, sz)                                                 \
    asm volatile("cp.async.ca.shared.global [%0], [%1], 16, %2;"                 \
                 :: "r"(dst), "l"(src), "r"(sz) : "memory")
#define CP_COMMIT()  asm volatile("cp.async.commit_group;" ::: "memory")
#define CP_WAIT_ALL() asm volatile("cp.async.wait_all;" ::: "memory")

// ---------------------------------------------------------------------------
// Split fp32 -> bf16 hi + lo (elementwise, float4)
// ---------------------------------------------------------------------------
__global__ __launch_bounds__(256)
void split_kernel(const float* __restrict__ in, __nv_bfloat16* __restrict__ hi,
                  __nv_bfloat16* __restrict__ lo, int n4)
{
    int i = blockIdx.x * blockDim.x + threadIdx.x;
    if (i >= n4) return;
    float4 x = ((const float4*)in)[i];
    __nv_bfloat16 h0 = __float2bfloat16_rn(x.x);
    __nv_bfloat16 h1 = __float2bfloat16_rn(x.y);
    __nv_bfloat16 h2 = __float2bfloat16_rn(x.z);
    __nv_bfloat16 h3 = __float2bfloat16_rn(x.w);
    __nv_bfloat16 l0 = __float2bfloat16_rn(x.x - __bfloat162float(h0));
    __nv_bfloat16 l1 = __float2bfloat16_rn(x.y - __bfloat162float(h1));
    __nv_bfloat16 l2 = __float2bfloat16_rn(x.z - __bfloat162float(h2));
    __nv_bfloat16 l3 = __float2bfloat16_rn(x.w - __bfloat162float(h3));
    ((__nv_bfloat162*)hi)[2 * i]     = __nv_bfloat162(h0, h1);
    ((__nv_bfloat162*)hi)[2 * i + 1] = __nv_bfloat162(h2, h3);
    ((__nv_bfloat162*)lo)[2 * i]     = __nv_bfloat162(l0, l1);
    ((__nv_bfloat162*)lo)[2 * i + 1] = __nv_bfloat162(l2, l3);
}

// ---------------------------------------------------------------------------
// Transpose + split weight: W[k][n] fp32 -> Wt_hi[n][k], Wt_lo[n][k] bf16
// ---------------------------------------------------------------------------
__global__ __launch_bounds__(256)
void wsplit_kernel(const float* __restrict__ W, __nv_bfloat16* __restrict__ hi,
                   __nv_bfloat16* __restrict__ lo)
{
    __shared__ float t[32][33];
    const int bx = blockIdx.x, by = blockIdx.y;
    const int tx = threadIdx.x, ty = threadIdx.y;   // 32 x 8
    #pragma unroll
    for (int i = 0; i < 32; i += 8)
        t[ty + i][tx] = W[(size_t)(by * 32 + ty + i) * 1024 + bx * 32 + tx];
    __syncthreads();
    #pragma unroll
    for (int i = 0; i < 32; i += 8) {
        float v = t[tx][ty + i];
        __nv_bfloat16 h = __float2bfloat16_rn(v);
        __nv_bfloat16 l = __float2bfloat16_rn(v - __bfloat162float(h));
        size_t o = (size_t)(bx * 32 + ty + i) * 1024 + by * 32 + tx;
        hi[o] = h;
        lo[o] = l;
    }
}

// ---------------------------------------------------------------------------
// Warp-MMA bf16-split GEMM, cp.async 2-stage double buffer.
// C[M,1024] = A[M,1024] * Bt[1024,1024]^T (+bias)
// Tile 128x128, BK=32; 8 warps 2(M)x4(N), each 64x32 via 4x4 m16n8k16.
// Per chunk 3 passes: Ah*Bh, Ah*Bl, Al*Bh (fp32 accum).
// Dynamic smem: 2 stages x 4 arrays x 128 x ST bf16.
// ---------------------------------------------------------------------------
#define ST 40                        // smem row stride in bf16 (80B)
#define ARR_B   (128 * ST * 2)       // bytes per array (10240)
#define STAGE_B (4 * ARR_B)          // bytes per stage (40960)
#define GSMEM   (2 * STAGE_B)        // total dynamic smem (81920)

extern __shared__ __nv_bfloat16 dynsmem[];

__global__ __launch_bounds__(256, 2)
void gemm_mma(int M, const __nv_bfloat16* __restrict__ aHi, const __nv_bfloat16* __restrict__ aLo,
              const __nv_bfloat16* __restrict__ btHi, const __nv_bfloat16* __restrict__ btLo,
              const float* __restrict__ bias, float* __restrict__ C)
{
    const int tid  = threadIdx.x;
    const int wid  = tid >> 5, lane = tid & 31;
    const int m0   = blockIdx.y * 128, n0 = blockIdx.x * 128;
    const int wm   = (wid >> 2) * 64;     // warp M origin
    const int wn   = (wid & 3) * 32;      // warp N origin

    const uint32_t sbase = smem_u32(dynsmem);

    float acc[4][4][4];
    #pragma unroll
    for (int mt = 0; mt < 4; mt++)
        #pragma unroll
        for (int nt = 0; nt < 4; nt++)
            #pragma unroll
            for (int e = 0; e < 4; e++) acc[mt][nt][e] = 0.0f;

    // cp.async fill: 2048 16B chunks per stage; idx = tid + i*256, i in 0..7
    // group = idx>>9 (0:Ah 1:Al 2:Bh 3:Bl), within = idx&511, row = within>>2, c16 = within&3
    #define LOAD_STAGE(c, sb) do {                                               \
        const int kk0 = (c) * 32;                                                \
        _Pragma("unroll")                                                        \
        for (int i = 0; i < 8; i++) {                                            \
            int idx = tid + i * 256;                                             \
            int grp = idx >> 9, within = idx & 511;                              \
            int row = within >> 2, c16 = within & 3;                             \
            int kc  = kk0 + c16 * 8;                                             \
            uint32_t dst = (sb) + grp * ARR_B + (row * ST + c16 * 8) * 2;        \
            const __nv_bfloat16* src;                                            \
            uint32_t sz = 16;                                                    \
            if (grp < 2) {                                                       \
                int m = m0 + row;                                                \
                if (m >= M) { m = m0; sz = 0; }                                  \
                src = (grp == 0 ? aHi : aLo) + (size_t)m * 1024 + kc;            \
            } else {                                                             \
                src = (grp == 2 ? btHi : btLo) + (size_t)(n0 + row) * 1024 + kc; \
            }                                                                    \
            CP_ASYNC16(dst, src, sz);                                            \
        }                                                                        \
        CP_COMMIT();                                                             \
    } while (0)

    LOAD_STAGE(0, sbase);

    // ldmatrix lane addressing
    const int aRow = wm + (lane & 15);
    const int aKof = (lane >> 4) * 8;
    const int bRow = wn + (lane & 7) + ((lane >> 4) << 3);   // x4 B: 2 n-tiles
    const int bKof = ((lane >> 3) & 1) * 8;

    for (int c = 0; c < 32; c++) {
        const uint32_t cur = sbase + (c & 1) * STAGE_B;
        CP_WAIT_ALL();
        __syncthreads();                 // stage c ready; MMA(c-1) done everywhere
        if (c < 31) LOAD_STAGE(c + 1, sbase + ((c + 1) & 1) * STAGE_B);

        const uint32_t Ah = cur, Al = cur + ARR_B;
        const uint32_t Bh = cur + 2 * ARR_B, Bl = cur + 3 * ARR_B;

        #pragma unroll
        for (int ks = 0; ks < 2; ks++) {
            const int kb = ks * 16;
            uint32_t ah[4][4], al[4][4], bh[2][4], bl[2][4];
            #pragma unroll
            for (int mt = 0; mt < 4; mt++) {
                uint32_t off = ((aRow + mt * 16) * ST + kb + aKof) * 2;
                LDM_X4(ah[mt][0], ah[mt][1], ah[mt][2], ah[mt][3], Ah + off);
                LDM_X4(al[mt][0], al[mt][1], al[mt][2], al[mt][3], Al + off);
            }
            #pragma unroll
            for (int p = 0; p < 2; p++) {
                uint32_t off = ((bRow + p * 16) * ST + kb + bKof) * 2;
                LDM_X4(bh[p][0], bh[p][1], bh[p][2], bh[p][3], Bh + off);
                LDM_X4(bl[p][0], bl[p][1], bl[p][2], bl[p][3], Bl + off);
            }
            #pragma unroll
            for (int mt = 0; mt < 4; mt++)
                #pragma unroll
                for (int nt = 0; nt < 4; nt++) {
                    const int p = nt >> 1, o = (nt & 1) * 2;
                    MMA_BF16(acc[mt][nt], ah[mt], bh[p][o], bh[p][o + 1]);
                    MMA_BF16(acc[mt][nt], ah[mt], bl[p][o], bl[p][o + 1]);
                    MMA_BF16(acc[mt][nt], al[mt], bh[p][o], bh[p][o + 1]);
                }
        }
        __syncthreads();                 // all warps done with stage c before refill
    }
    #undef LOAD_STAGE

    // epilogue
    const int r     = lane >> 2;
    const int cpair = (lane & 3) * 2;
    #pragma unroll
    for (int nt = 0; nt < 4; nt++) {
        const int n  = n0 + wn + nt * 8 + cpair;
        float b0 = 0.f, b1 = 0.f;
        if (bias) { b0 = bias[n]; b1 = bias[n + 1]; }
        #pragma unroll
        for (int mt = 0; mt < 4; mt++) {
            const int m = m0 + wm + mt * 16 + r;
            if (m < M) {
                float2 v0 = make_float2(acc[mt][nt][0] + b0, acc[mt][nt][1] + b1);
                *(float2*)(C + (size_t)m * 1024 + n) = v0;
            }
            if (m + 8 < M) {
                float2 v1 = make_float2(acc[mt][nt][2] + b0, acc[mt][nt][3] + b1);
                *(float2*)(C + (size_t)(m + 8) * 1024 + n) = v1;
            }
        }
    }
}

// ---------------------------------------------------------------------------
// LayerNorm over rows of 1024, output split directly to bf16 hi/lo
// ---------------------------------------------------------------------------
__global__ __launch_bounds__(256)
void ln_split_kernel(const float* __restrict__ in, const float* __restrict__ gamma,
                     const float* __restrict__ beta, __nv_bfloat16* __restrict__ hi,
                     __nv_bfloat16* __restrict__ lo)
{
    const int row = blockIdx.x;
    const int t   = threadIdx.x;
    const float4* x4 = (const float4*)(in + (size_t)row * PD);
    float4 xv = x4[t];

    float s  = xv.x + xv.y + xv.z + xv.w;
    float s2 = xv.x * xv.x + xv.y * xv.y + xv.z * xv.z + xv.w * xv.w;

    __shared__ float red[2][8];
    #pragma unroll
    for (int o = 16; o > 0; o >>= 1) {
        s  += __shfl_down_sync(0xFFFFFFFFu, s,  o);
        s2 += __shfl_down_sync(0xFFFFFFFFu, s2, o);
    }
    const int wid = t >> 5, lid = t & 31;
    if (lid == 0) { red[0][wid] = s; red[1][wid] = s2; }
    __syncthreads();
    if (wid == 0) {
        float a = (lid < 8) ? red[0][lid] : 0.f;
        float b = (lid < 8) ? red[1][lid] : 0.f;
        #pragma unroll
        for (int o = 4; o > 0; o >>= 1) {
            a += __shfl_down_sync(0xFFFFFFFFu, a, o);
            b += __shfl_down_sync(0xFFFFFFFFu, b, o);
        }
        if (lid == 0) { red[0][0] = a; red[1][0] = b; }
    }
    __syncthreads();

    const float mean = red[0][0] * (1.0f / PD);
    const float var  = red[1][0] * (1.0f / PD) - mean * mean;
    const float rstd = rsqrtf(var + 1e-5f);

    float4 gv = ((const float4*)gamma)[t];
    float4 bv = ((const float4*)beta)[t];
    float o0 = (xv.x - mean) * rstd * gv.x + bv.x;
    float o1 = (xv.y - mean) * rstd * gv.y + bv.y;
    float o2 = (xv.z - mean) * rstd * gv.z + bv.z;
    float o3 = (xv.w - mean) * rstd * gv.w + bv.w;

    __nv_bfloat16 h0 = __float2bfloat16_rn(o0);
    __nv_bfloat16 h1 = __float2bfloat16_rn(o1);
    __nv_bfloat16 h2 = __float2bfloat16_rn(o2);
    __nv_bfloat16 h3 = __float2bfloat16_rn(o3);
    __nv_bfloat16 l0 = __float2bfloat16_rn(o0 - __bfloat162float(h0));
    __nv_bfloat16 l1 = __float2bfloat16_rn(o1 - __bfloat162float(h1));
    __nv_bfloat16 l2 = __float2bfloat16_rn(o2 - __bfloat162float(h2));
    __nv_bfloat16 l3 = __float2bfloat16_rn(o3 - __bfloat162float(h3));

    const size_t o = (size_t)row * PD / 2 + 2 * t;
    ((__nv_bfloat162*)hi)[o]     = __nv_bfloat162(h0, h1);
    ((__nv_bfloat162*)hi)[o + 1] = __nv_bfloat162(h2, h3);
    ((__nv_bfloat162*)lo)[o]     = __nv_bfloat162(l0, l1);
    ((__nv_bfloat162*)lo)[o + 1] = __nv_bfloat162(l2, l3);
}

// ---------------------------------------------------------------------------
// Temporal attention (att_type == 1). Reference tile quirk: feature K/V for
// attention batch b = nh*S + s comes from head-batch (b % 64).
// ---------------------------------------------------------------------------
__global__ __launch_bounds__(128)
void attn_kernel(const float* __restrict__ Q, const float* __restrict__ Kt,
                 const float* __restrict__ Vt, float* __restrict__ O)
{
    constexpr int PITCH = 129;
    __shared__ float qs[16 * PITCH];
    __shared__ float ks[17 * PITCH];
    __shared__ float vs[17 * PITCH];
    __shared__ float ps[16 * 18];

    const int s  = blockIdx.x;         // 0..195
    const int nh = blockIdx.y;         // 0..63
    const int n  = nh >> 3;
    const int h  = nh & 7;
    const int t  = threadIdx.x;        // 0..127

    const int fb = (nh * PS + s) & 63;
    const int fn = fb >> 3;
    const int fh = fb & 7;
    const size_t featKV = ((size_t)fn * PL) * PD + (size_t)fh * PHD;
    ks[t] = Kt[featKV + t];
    vs[t] = Vt[featKV + t];

    for (int f = 0; f < PF; f++) {
        const size_t r = ((size_t)n * PL + 1 + (size_t)f * PS + s) * PD + (size_t)h * PHD;
        qs[f * PITCH + t]       = Q [r + t];
        ks[(f + 1) * PITCH + t] = Kt[r + t];
        vs[(f + 1) * PITCH + t] = Vt[r + t];
    }
    __syncthreads();

    const float scale = 0.088388347648318447f;   // 1/sqrt(128)
    for (int p = t; p < 16 * 17; p += 128) {
        const int i = p / 17, j = p % 17;
        float acc = 0.f;
        #pragma unroll 8
        for (int d = 0; d < PHD; d++)
            acc = fmaf(qs[i * PITCH + d], ks[j * PITCH + d], acc);
        ps[i * 18 + j] = acc * scale;
    }
    __syncthreads();

    if (t < 16) {
        float mx = -1e30f;
        #pragma unroll
        for (int j = 0; j < 17; j++) mx = fmaxf(mx, ps[t * 18 + j]);
        float sum = 0.f;
        #pragma unroll
        for (int j = 0; j < 17; j++) {
            const float e = __expf(ps[t * 18 + j] - mx);
            ps[t * 18 + j] = e;
            sum += e;
        }
        const float inv = 1.0f / sum;
        #pragma unroll
        for (int j = 0; j < 17; j++) ps[t * 18 + j] *= inv;
    }
    __syncthreads();

    for (int i = 0; i < PF; i++) {
        float acc = 0.f;
        #pragma unroll
        for (int j = 0; j < 17; j++)
            acc = fmaf(ps[i * 18 + j], vs[j * PITCH + t], acc);
        O[((size_t)n * PL + 1 + (size_t)i * PS + s) * PD + (size_t)h * PHD + t] = acc;
    }

    if (s == 0) {
        const size_t featRow = ((size_t)n * PL) * PD + (size_t)h * PHD;
        O[featRow + t] = Q[featRow + t];
    }
}

// ---------------------------------------------------------------------------
// Launch
// ---------------------------------------------------------------------------
extern "C" void kernel_launch(void* const* d_in, const int* in_sizes, int n_in,
                              void* d_out, int out_size)
{
    (void)in_sizes; (void)n_in; (void)out_size;

    const float* x        = (const float*)d_in[0];
    const float* W_in     = (const float*)d_in[1];
    const float* b_in     = (const float*)d_in[2];
    const float* g_in     = (const float*)d_in[3];
    const float* beta_in  = (const float*)d_in[4];
    const float* W_q      = (const float*)d_in[5];
    const float* W_k      = (const float*)d_in[6];
    const float* W_v      = (const float*)d_in[7];
    const float* g_out    = (const float*)d_in[8];
    const float* beta_out = (const float*)d_in[9];
    const float* W_out    = (const float*)d_in[10];
    const float* b_out    = (const float*)d_in[11];
    float* out = (float*)d_out;

    float *t0, *q, *k, *v;
    __nv_bfloat16 *ahi, *alo, *wth, *wtl;
    cudaGetSymbolAddress((void**)&t0,  g_t0);
    cudaGetSymbolAddress((void**)&q,   g_q);
    cudaGetSymbolAddress((void**)&k,   g_k);
    cudaGetSymbolAddress((void**)&v,   g_v);
    cudaGetSymbolAddress((void**)&ahi, g_ahi);
    cudaGetSymbolAddress((void**)&alo, g_alo);
    cudaGetSymbolAddress((void**)&wth, g_wth);
    cudaGetSymbolAddress((void**)&wtl, g_wtl);

    cudaFuncSetAttribute(gemm_mma, cudaFuncAttributeMaxDynamicSharedMemorySize, GSMEM);

    const size_t WSLOT = 1024ull * 1024ull;
    const dim3 wsGrid(32, 32), wsBlk(32, 8);
    const int n4 = PNL * PD / 4;
    const int splitBlocks = (n4 + 255) / 256;
    const dim3 gemmGrid(8, 197);      // (N-tiles, M-tiles)
    const dim3 gemmBlk(256);

    // weight transforms (W_out deferred so gemm_mma is launch index 5 for ncu)
    wsplit_kernel<<<wsGrid, wsBlk>>>(W_in,  wth + 0 * WSLOT, wtl + 0 * WSLOT);
    wsplit_kernel<<<wsGrid, wsBlk>>>(W_q,   wth + 1 * WSLOT, wtl + 1 * WSLOT);
    wsplit_kernel<<<wsGrid, wsBlk>>>(W_k,   wth + 2 * WSLOT, wtl + 2 * WSLOT);
    wsplit_kernel<<<wsGrid, wsBlk>>>(W_v,   wth + 3 * WSLOT, wtl + 3 * WSLOT);

    // 1. t0 = x @ W_in + b_in
    split_kernel<<<splitBlocks, 256>>>(x, ahi, alo, n4);
    gemm_mma<<<gemmGrid, gemmBlk, GSMEM>>>(PNL, ahi, alo, wth + 0 * WSLOT, wtl + 0 * WSLOT, b_in, t0);
    // 2. (ahi, alo) = split(LN(t0))
    ln_split_kernel<<<PNL, 256>>>(t0, g_in, beta_in, ahi, alo);
    // 3. q/k/v projections
    gemm_mma<<<gemmGrid, gemmBlk, GSMEM>>>(PNL, ahi, alo, wth + 1 * WSLOT, wtl + 1 * WSLOT, nullptr, q);
    gemm_mma<<<gemmGrid, gemmBlk, GSMEM>>>(PNL, ahi, alo, wth + 2 * WSLOT, wtl + 2 * WSLOT, nullptr, k);
    gemm_mma<<<gemmGrid, gemmBlk, GSMEM>>>(PNL, ahi, alo, wth + 3 * WSLOT, wtl + 3 * WSLOT, nullptr, v);
    // 4. temporal attention -> t0
    attn_kernel<<<dim3(PS, PN * PH), 128>>>(q, k, v, t0);
    // 5. (ahi, alo) = split(LN(t0))
    ln_split_kernel<<<PNL, 256>>>(t0, g_out, beta_out, ahi, alo);
    // 6. out = x1 @ W_out + b_out
    wsplit_kernel<<<wsGrid, wsBlk>>>(W_out, wth + 4 * WSLOT, wtl + 4 * WSLOT);
    gemm_mma<<<gemmGrid, gemmBlk, GSMEM>>>(PNL, ahi, alo, wth + 4 * WSLOT, wtl + 4 * WSLOT, b_out, out);
}